// round 9
// baseline (speedup 1.0000x reference)
#include <cuda_runtime.h>

// EGNN layer, B=4, N=512, D=64, H=1.
// R9: 2 launches. prep (node proj + WhhT transpose + P/Q), then fused
// edge+GRU (block owns node i end-to-end; GRU reads coalesced WhhT, gi is
// rank-1 in S via P/Q). R8 analysis: runtime is launch-ramp dominated.

#define BB 4
#define NN 512
#define DD 64
#define NNODE (BB * NN)

#define NPROJ_BLOCKS (NNODE / 4)        // 512
#define TRANS_BLOCKS 48                 // 12288 / 256
#define PQ_BLOCKS    24                 // 192 warps

__device__ float g_a   [NNODE];
__device__ float g_bb  [NNODE];
__device__ float g_WhhT[DD * 3 * DD];   // [k][r]  (64 x 192)
__device__ float g_P   [3 * DD];
__device__ float g_Q   [3 * DD];

__device__ __forceinline__ float tanh_ap(float x) {
    float y;
    asm("tanh.approx.f32 %0, %1;" : "=f"(y) : "f"(x));
    return y;
}
__device__ __forceinline__ float sigmoid_f(float x) {
    return fmaf(tanh_ap(0.5f * x), 0.5f, 0.5f);
}
__device__ __forceinline__ float silu_f(float x) {
    return x * sigmoid_f(x);
}

// ---------------------------------------------------------------------------
// Kernel 1: prep.
// ---------------------------------------------------------------------------
__global__ __launch_bounds__(256) void prep_kernel(
    const float* __restrict__ h,   const float* __restrict__ eW1,
    const float* __restrict__ nW2, const float* __restrict__ nb2,
    const float* __restrict__ Wih, const float* __restrict__ bih,
    const float* __restrict__ Whh)
{
    const int tid = threadIdx.x;
    const int bid = blockIdx.x;

    if (bid < NPROJ_BLOCKS) {
        const int g    = tid >> 6;
        const int t    = tid & 63;
        const int node = bid * 4 + g;
        const float hv = h[node * DD + t];
        float pa = hv * eW1[t];
        float pb = hv * eW1[DD + t];
        #pragma unroll
        for (int o = 16; o > 0; o >>= 1) {
            pa += __shfl_down_sync(0xffffffffu, pa, o);
            pb += __shfl_down_sync(0xffffffffu, pb, o);
        }
        __shared__ float sa[8], sb[8];
        const int w = tid >> 5;
        if ((tid & 31) == 0) { sa[w] = pa; sb[w] = pb; }
        __syncthreads();
        if (t == 0) {
            g_a [node] = sa[2 * g] + sa[2 * g + 1];
            g_bb[node] = sb[2 * g] + sb[2 * g + 1];
        }
    } else if (bid < NPROJ_BLOCKS + TRANS_BLOCKS) {
        const int o = (bid - NPROJ_BLOCKS) * 256 + tid;   // o = k*192 + r
        const int k = o / (3 * DD);
        const int r = o - k * (3 * DD);
        g_WhhT[o] = Whh[r * DD + k];
    } else {
        const int warp = (bid - NPROJ_BLOCKS - TRANS_BLOCKS) * 8 + (tid >> 5);
        const int lane = tid & 31;
        if (warp < 3 * DD) {
            const float* __restrict__ Wr = Wih + (size_t)warp * DD;
            const float w0 = Wr[lane], w1 = Wr[32 + lane];
            float p = fmaf(w1, nW2[32 + lane], w0 * nW2[lane]);
            float q = fmaf(w1, (float)NN * nb2[32 + lane],
                           w0 * ((float)NN * nb2[lane]));
            #pragma unroll
            for (int o = 16; o > 0; o >>= 1) {
                p += __shfl_down_sync(0xffffffffu, p, o);
                q += __shfl_down_sync(0xffffffffu, q, o);
            }
            if (lane == 0) {
                g_P[warp] = p;
                g_Q[warp] = q + bih[warp];
            }
        }
    }
}

// ---------------------------------------------------------------------------
// Kernel 2 (fused): edge loop + x_new + GRU.  One node i per block.
// ---------------------------------------------------------------------------
__global__ __launch_bounds__(256) void edge_gru_kernel(
    const float* __restrict__ h,
    const float* __restrict__ x,
    const float* __restrict__ rij,
    const float* __restrict__ dij,
    const float* __restrict__ mask,
    const float* __restrict__ eW1, const float* __restrict__ eb1,
    const float* __restrict__ eW2, const float* __restrict__ eb2,
    const float* __restrict__ eW3, const float* __restrict__ eb3,
    const float* __restrict__ pW1, const float* __restrict__ pb1,
    const float* __restrict__ pW2, const float* __restrict__ pb2,
    const float* __restrict__ nW1, const float* __restrict__ nb1,
    const float* __restrict__ bhh,
    float* __restrict__ out)
{
    const int node = blockIdx.x;
    const int b    = node / NN;
    const int tid  = threadIdx.x;

    __shared__ float red[8][4];
    __shared__ float hs[DD];
    __shared__ float gh[3 * DD];
    __shared__ float gi[3 * DD];
    __shared__ float sS;

    // stage h row early (overlaps with edge math)
    if (tid < DD) hs[tid] = h[node * DD + tid];

    const float wd    = eW1[2 * DD];
    const float c_eb1 = eb1[0];
    const float c_eW2 = eW2[0], c_eb2 = eb2[0];
    const float c_eW3 = eW3[0], c_eb3 = eb3[0];
    const float c_pW1 = pW1[0], c_pb1 = pb1[0];
    const float c_pW2 = pW2[0], c_pb2 = pb2[0];
    const float c_nW1 = nW1[0], c_nb1 = nb1[0];

    const float mi  = mask[node];
    const float aib = g_a[node] + c_eb1;

    const float2* __restrict__ d2 = (const float2*)(dij + (size_t)node * NN);
    const float2* __restrict__ r2 = (const float2*)(rij + (size_t)node * NN * 3);
    const float2* __restrict__ b2 = (const float2*)(g_bb + b * NN);
    const float2* __restrict__ k2 = (const float2*)(mask + b * NN);

    const float2 dv = d2[tid];
    const float2 bv = b2[tid];
    const float2 kv = k2[tid];
    const float2 ra = r2[3 * tid + 0];
    const float2 rb = r2[3 * tid + 1];
    const float2 rc = r2[3 * tid + 2];

    float x0, x1, x2, S;
    {
        float s  = fmaf(dv.x, wd, aib + bv.x);
        float u  = silu_f(fmaf(silu_f(s), c_eW2, c_eb2));
        float mu = fmaf(u, c_eW3, c_eb3) * mi * kv.x;
        float ph = fmaf(silu_f(fmaf(mu, c_pW1, c_pb1)), c_pW2, c_pb2);
        S  = silu_f(fmaf(mu, c_nW1, c_nb1));
        x0 = ra.x * ph;
        x1 = ra.y * ph;
        x2 = rb.x * ph;
    }
    {
        float s  = fmaf(dv.y, wd, aib + bv.y);
        float u  = silu_f(fmaf(silu_f(s), c_eW2, c_eb2));
        float mu = fmaf(u, c_eW3, c_eb3) * mi * kv.y;
        float ph = fmaf(silu_f(fmaf(mu, c_pW1, c_pb1)), c_pW2, c_pb2);
        S += silu_f(fmaf(mu, c_nW1, c_nb1));
        x0 = fmaf(rb.y, ph, x0);
        x1 = fmaf(rc.x, ph, x1);
        x2 = fmaf(rc.y, ph, x2);
    }

    #pragma unroll
    for (int o = 16; o > 0; o >>= 1) {
        x0 += __shfl_down_sync(0xffffffffu, x0, o);
        x1 += __shfl_down_sync(0xffffffffu, x1, o);
        x2 += __shfl_down_sync(0xffffffffu, x2, o);
        S  += __shfl_down_sync(0xffffffffu, S , o);
    }
    const int wid = tid >> 5;
    if ((tid & 31) == 0) {
        red[wid][0] = x0; red[wid][1] = x1; red[wid][2] = x2; red[wid][3] = S;
    }
    __syncthreads();
    if (tid == 0) {
        float r0 = 0.f, r1 = 0.f, r2s = 0.f, rs = 0.f;
        #pragma unroll
        for (int w = 0; w < 8; w++) {
            r0 += red[w][0]; r1 += red[w][1]; r2s += red[w][2]; rs += red[w][3];
        }
        sS = rs;
        float* xo = out + (size_t)NNODE * DD + (size_t)node * 3;
        xo[0] = x[node * 3 + 0] + r0;
        xo[1] = x[node * 3 + 1] + r1;
        xo[2] = x[node * 3 + 2] + r2s;
    }
    __syncthreads();

    // --- GRU phase 1: 192 threads, one gate-output r each ---
    // gh[r] = bhh[r] + sum_k WhhT[k][r] * hs[k]   (WhhT coalesced, hs broadcast)
    // gi[r] = S*P[r] + Q[r]
    if (tid < 3 * DD) {
        const int r = tid;
        const float Sv = sS;
        float acc = bhh[r];
        const float* __restrict__ WT = g_WhhT + r;
        #pragma unroll 8
        for (int k = 0; k < DD; k++) {
            acc = fmaf(WT[k * (3 * DD)], hs[k], acc);
        }
        gh[r] = acc;
        gi[r] = fmaf(Sv, g_P[r], g_Q[r]);
    }
    __syncthreads();

    // --- GRU phase 2: 64 threads, elementwise gates ---
    if (tid < DD) {
        const int d = tid;
        const float r = sigmoid_f(gi[d] + gh[d]);
        const float z = sigmoid_f(gi[DD + d] + gh[DD + d]);
        const float n = tanh_ap(fmaf(r, gh[2 * DD + d], gi[2 * DD + d]));
        const float hnew = (1.0f - z) * n + z * hs[d];
        out[node * DD + d] = hnew * mi;
    }
}

// ---------------------------------------------------------------------------
extern "C" void kernel_launch(void* const* d_in, const int* in_sizes, int n_in,
                              void* d_out, int out_size) {
    const float* h    = (const float*)d_in[0];
    const float* x    = (const float*)d_in[1];
    const float* rij  = (const float*)d_in[2];
    const float* dij  = (const float*)d_in[3];
    const float* mask = (const float*)d_in[4];
    const float* eW1  = (const float*)d_in[5];
    const float* eb1  = (const float*)d_in[6];
    const float* eW2  = (const float*)d_in[7];
    const float* eb2  = (const float*)d_in[8];
    const float* eW3  = (const float*)d_in[9];
    const float* eb3  = (const float*)d_in[10];
    const float* pW1  = (const float*)d_in[11];
    const float* pb1  = (const float*)d_in[12];
    const float* pW2  = (const float*)d_in[13];
    const float* pb2  = (const float*)d_in[14];
    const float* nW1  = (const float*)d_in[15];
    const float* nb1  = (const float*)d_in[16];
    const float* nW2  = (const float*)d_in[17];
    const float* nb2  = (const float*)d_in[18];
    const float* Wih  = (const float*)d_in[19];
    const float* bih  = (const float*)d_in[20];
    const float* Whh  = (const float*)d_in[21];
    const float* bhh  = (const float*)d_in[22];
    float* out = (float*)d_out;

    prep_kernel<<<NPROJ_BLOCKS + TRANS_BLOCKS + PQ_BLOCKS, 256>>>(
        h, eW1, nW2, nb2, Wih, bih, Whh);
    edge_gru_kernel<<<NNODE, 256>>>(h, x, rij, dij, mask,
                                    eW1, eb1, eW2, eb2, eW3, eb3,
                                    pW1, pb1, pW2, pb2, nW1, nb1,
                                    bhh, out);
}

// round 10
// speedup vs baseline: 1.3534x; 1.3534x over previous
#include <cuda_runtime.h>

// EGNN layer, B=4, N=512, D=64, H=1.
// R10: hoist GRU matvec (gh = Whh@h + bhh) out of the per-node hot kernel into
// a batched smem-tiled GEMM in prep (it only depends on h). Edge kernel's GRU
// tail becomes 3 coalesced loads + gates. R9 profile: per-block GRU matvec was
// 384/480 L1 wavefronts per block and ~43% of issued instructions.

#define BB 4
#define NN 512
#define DD 64
#define NNODE (BB * NN)

#define GH_BLOCKS   128          // 16 nodes each
#define PQ_BLOCKS   24           // 192 warps
#define NODES_PER_GH 16

__device__ float g_a  [NNODE];
__device__ float g_bb [NNODE];
__device__ float g_gh [NNODE * 3 * DD];  // bhh + Whh @ h per node (192 each)
__device__ float g_P  [3 * DD];
__device__ float g_Q  [3 * DD];

__device__ __forceinline__ float tanh_ap(float x) {
    float y;
    asm("tanh.approx.f32 %0, %1;" : "=f"(y) : "f"(x));
    return y;
}
__device__ __forceinline__ float sigmoid_f(float x) {
    return fmaf(tanh_ap(0.5f * x), 0.5f, 0.5f);
}
__device__ __forceinline__ float silu_f(float x) {
    return x * sigmoid_f(x);
}

// ---------------------------------------------------------------------------
// Kernel 1: prep (152 blocks, one wave).
//   blocks [0,128):  gh GEMM for 16 nodes + node projections a/b (threads 192+)
//   blocks [128,152): P/Q (warp per output row)
// ---------------------------------------------------------------------------
__global__ __launch_bounds__(256) void prep_kernel(
    const float* __restrict__ h,   const float* __restrict__ eW1,
    const float* __restrict__ nW2, const float* __restrict__ nb2,
    const float* __restrict__ Wih, const float* __restrict__ bih,
    const float* __restrict__ Whh, const float* __restrict__ bhh)
{
    const int tid = threadIdx.x;
    const int bid = blockIdx.x;

    if (bid < GH_BLOCKS) {
        // smem: half-K Whh tile (XOR-swizzled), h for 16 nodes, eW1
        __shared__ float wsh[(3 * DD) * 32];   // 24 KB: Whh[:, khalf]
        __shared__ float hs[NODES_PER_GH * DD];// 4 KB
        __shared__ float se1[2 * DD];          // 512 B

        const int node0 = bid * NODES_PER_GH;

        // stage hs (float4) + se1 + wsh phase 0
        {
            const float4* h4 = (const float4*)(h + (size_t)node0 * DD);
            ((float4*)hs)[tid] = h4[tid];
            if (tid < 2 * DD) se1[tid] = eW1[tid];
            #pragma unroll
            for (int i = 0; i < 6; i++) {
                const int e4 = tid + i * 256;          // float4 index, < 1536
                const int r  = e4 >> 3;                // 0..191
                const int k4 = (e4 & 7) * 4;           // 0..28
                const float4 v = *(const float4*)(Whh + (size_t)r * DD + k4);
                const int rx = r & 31;
                wsh[r * 32 + ((k4 + 0) ^ rx)] = v.x;
                wsh[r * 32 + ((k4 + 1) ^ rx)] = v.y;
                wsh[r * 32 + ((k4 + 2) ^ rx)] = v.z;
                wsh[r * 32 + ((k4 + 3) ^ rx)] = v.w;
            }
        }
        __syncthreads();

        float acc[NODES_PER_GH];
        if (tid < 3 * DD) {
            const int r  = tid;
            const int rx = r & 31;
            const float* wr = wsh + r * 32;
            #pragma unroll
            for (int n = 0; n < NODES_PER_GH; n++) acc[n] = 0.f;
            #pragma unroll 8
            for (int k = 0; k < 32; k++) {
                const float w = wr[k ^ rx];
                #pragma unroll
                for (int n = 0; n < NODES_PER_GH; n++)
                    acc[n] = fmaf(w, hs[n * DD + k], acc[n]);
            }
        } else {
            // node projections: 64 threads, 32 dots (16 nodes x {a,b}),
            // 2 threads per dot (k halves)
            const int u     = tid - 3 * DD;     // 0..63
            const int dot   = u >> 1;           // 0..31
            const int n     = dot >> 1;
            const int which = dot & 1;
            const int k0    = (u & 1) * 32;
            float p = 0.f;
            const float* hv = hs + n * DD + k0;
            const float* wv = se1 + which * DD + k0;
            #pragma unroll 8
            for (int kk = 0; kk < 32; kk++)
                p = fmaf(hv[kk], wv[kk], p);
            p += __shfl_down_sync(0xffffffffu, p, 1);
            if ((u & 1) == 0) {
                if (which == 0) g_a [node0 + n] = p;
                else            g_bb[node0 + n] = p;
            }
        }
        __syncthreads();

        // stage wsh phase 1 (k in [32,64))
        #pragma unroll
        for (int i = 0; i < 6; i++) {
            const int e4 = tid + i * 256;
            const int r  = e4 >> 3;
            const int k4 = (e4 & 7) * 4;
            const float4 v = *(const float4*)(Whh + (size_t)r * DD + 32 + k4);
            const int rx = r & 31;
            wsh[r * 32 + ((k4 + 0) ^ rx)] = v.x;
            wsh[r * 32 + ((k4 + 1) ^ rx)] = v.y;
            wsh[r * 32 + ((k4 + 2) ^ rx)] = v.z;
            wsh[r * 32 + ((k4 + 3) ^ rx)] = v.w;
        }
        __syncthreads();

        if (tid < 3 * DD) {
            const int r  = tid;
            const int rx = r & 31;
            const float* wr = wsh + r * 32;
            #pragma unroll 8
            for (int k = 0; k < 32; k++) {
                const float w = wr[k ^ rx];
                #pragma unroll
                for (int n = 0; n < NODES_PER_GH; n++)
                    acc[n] = fmaf(w, hs[n * DD + 32 + k], acc[n]);
            }
            const float bh = bhh[r];
            #pragma unroll
            for (int n = 0; n < NODES_PER_GH; n++)
                g_gh[(size_t)(node0 + n) * (3 * DD) + r] = acc[n] + bh;
        }
    } else {
        // P/Q: warp per output row r
        const int warp = (bid - GH_BLOCKS) * 8 + (tid >> 5);
        const int lane = tid & 31;
        if (warp < 3 * DD) {
            const float* __restrict__ Wr = Wih + (size_t)warp * DD;
            const float w0 = Wr[lane], w1 = Wr[32 + lane];
            float p = fmaf(w1, nW2[32 + lane], w0 * nW2[lane]);
            float q = fmaf(w1, (float)NN * nb2[32 + lane],
                           w0 * ((float)NN * nb2[lane]));
            #pragma unroll
            for (int o = 16; o > 0; o >>= 1) {
                p += __shfl_down_sync(0xffffffffu, p, o);
                q += __shfl_down_sync(0xffffffffu, q, o);
            }
            if (lane == 0) {
                g_P[warp] = p;
                g_Q[warp] = q + bih[warp];
            }
        }
    }
}

// ---------------------------------------------------------------------------
// Kernel 2: edge loop + x_new + GRU gates.  One node i per block.
// ---------------------------------------------------------------------------
__global__ __launch_bounds__(256) void edge_gru_kernel(
    const float* __restrict__ h,
    const float* __restrict__ x,
    const float* __restrict__ rij,
    const float* __restrict__ dij,
    const float* __restrict__ mask,
    const float* __restrict__ eW1, const float* __restrict__ eb1,
    const float* __restrict__ eW2, const float* __restrict__ eb2,
    const float* __restrict__ eW3, const float* __restrict__ eb3,
    const float* __restrict__ pW1, const float* __restrict__ pb1,
    const float* __restrict__ pW2, const float* __restrict__ pb2,
    const float* __restrict__ nW1, const float* __restrict__ nb1,
    float* __restrict__ out)
{
    const int node = blockIdx.x;
    const int b    = node / NN;
    const int tid  = threadIdx.x;

    __shared__ float red[8][4];
    __shared__ float hs[DD];
    __shared__ float sS;

    if (tid < DD) hs[tid] = h[node * DD + tid];

    const float wd    = eW1[2 * DD];
    const float c_eb1 = eb1[0];
    const float c_eW2 = eW2[0], c_eb2 = eb2[0];
    const float c_eW3 = eW3[0], c_eb3 = eb3[0];
    const float c_pW1 = pW1[0], c_pb1 = pb1[0];
    const float c_pW2 = pW2[0], c_pb2 = pb2[0];
    const float c_nW1 = nW1[0], c_nb1 = nb1[0];

    const float mi  = mask[node];
    const float aib = g_a[node] + c_eb1;

    const float2* __restrict__ d2 = (const float2*)(dij + (size_t)node * NN);
    const float2* __restrict__ r2 = (const float2*)(rij + (size_t)node * NN * 3);
    const float2* __restrict__ b2 = (const float2*)(g_bb + b * NN);
    const float2* __restrict__ k2 = (const float2*)(mask + b * NN);

    const float2 dv = d2[tid];
    const float2 bv = b2[tid];
    const float2 kv = k2[tid];
    const float2 ra = r2[3 * tid + 0];
    const float2 rb = r2[3 * tid + 1];
    const float2 rc = r2[3 * tid + 2];

    float x0, x1, x2, S;
    {
        float s  = fmaf(dv.x, wd, aib + bv.x);
        float u  = silu_f(fmaf(silu_f(s), c_eW2, c_eb2));
        float mu = fmaf(u, c_eW3, c_eb3) * mi * kv.x;
        float ph = fmaf(silu_f(fmaf(mu, c_pW1, c_pb1)), c_pW2, c_pb2);
        S  = silu_f(fmaf(mu, c_nW1, c_nb1));
        x0 = ra.x * ph;
        x1 = ra.y * ph;
        x2 = rb.x * ph;
    }
    {
        float s  = fmaf(dv.y, wd, aib + bv.y);
        float u  = silu_f(fmaf(silu_f(s), c_eW2, c_eb2));
        float mu = fmaf(u, c_eW3, c_eb3) * mi * kv.y;
        float ph = fmaf(silu_f(fmaf(mu, c_pW1, c_pb1)), c_pW2, c_pb2);
        S += silu_f(fmaf(mu, c_nW1, c_nb1));
        x0 = fmaf(rb.y, ph, x0);
        x1 = fmaf(rc.x, ph, x1);
        x2 = fmaf(rc.y, ph, x2);
    }

    #pragma unroll
    for (int o = 16; o > 0; o >>= 1) {
        x0 += __shfl_down_sync(0xffffffffu, x0, o);
        x1 += __shfl_down_sync(0xffffffffu, x1, o);
        x2 += __shfl_down_sync(0xffffffffu, x2, o);
        S  += __shfl_down_sync(0xffffffffu, S , o);
    }
    const int wid = tid >> 5;
    if ((tid & 31) == 0) {
        red[wid][0] = x0; red[wid][1] = x1; red[wid][2] = x2; red[wid][3] = S;
    }
    __syncthreads();
    if (tid == 0) {
        float r0 = 0.f, r1 = 0.f, r2s = 0.f, rs = 0.f;
        #pragma unroll
        for (int w = 0; w < 8; w++) {
            r0 += red[w][0]; r1 += red[w][1]; r2s += red[w][2]; rs += red[w][3];
        }
        sS = rs;
        float* xo = out + (size_t)NNODE * DD + (size_t)node * 3;
        xo[0] = x[node * 3 + 0] + r0;
        xo[1] = x[node * 3 + 1] + r1;
        xo[2] = x[node * 3 + 2] + r2s;
    }
    __syncthreads();

    // --- GRU gates: gh precomputed, gi rank-1 in S ---
    if (tid < DD) {
        const int d  = tid;
        const float Sv = sS;
        const float* gh = g_gh + (size_t)node * (3 * DD);
        const float ghr = gh[d];
        const float ghz = gh[DD + d];
        const float ghn = gh[2 * DD + d];
        const float gir = fmaf(Sv, g_P[d],          g_Q[d]);
        const float giz = fmaf(Sv, g_P[DD + d],     g_Q[DD + d]);
        const float gin = fmaf(Sv, g_P[2 * DD + d], g_Q[2 * DD + d]);
        const float r = sigmoid_f(gir + ghr);
        const float z = sigmoid_f(giz + ghz);
        const float n = tanh_ap(fmaf(r, ghn, gin));
        const float hnew = (1.0f - z) * n + z * hs[d];
        out[node * DD + d] = hnew * mi;
    }
}

// ---------------------------------------------------------------------------
extern "C" void kernel_launch(void* const* d_in, const int* in_sizes, int n_in,
                              void* d_out, int out_size) {
    const float* h    = (const float*)d_in[0];
    const float* x    = (const float*)d_in[1];
    const float* rij  = (const float*)d_in[2];
    const float* dij  = (const float*)d_in[3];
    const float* mask = (const float*)d_in[4];
    const float* eW1  = (const float*)d_in[5];
    const float* eb1  = (const float*)d_in[6];
    const float* eW2  = (const float*)d_in[7];
    const float* eb2  = (const float*)d_in[8];
    const float* eW3  = (const float*)d_in[9];
    const float* eb3  = (const float*)d_in[10];
    const float* pW1  = (const float*)d_in[11];
    const float* pb1  = (const float*)d_in[12];
    const float* pW2  = (const float*)d_in[13];
    const float* pb2  = (const float*)d_in[14];
    const float* nW1  = (const float*)d_in[15];
    const float* nb1  = (const float*)d_in[16];
    const float* nW2  = (const float*)d_in[17];
    const float* nb2  = (const float*)d_in[18];
    const float* Wih  = (const float*)d_in[19];
    const float* bih  = (const float*)d_in[20];
    const float* Whh  = (const float*)d_in[21];
    const float* bhh  = (const float*)d_in[22];
    float* out = (float*)d_out;

    prep_kernel<<<GH_BLOCKS + PQ_BLOCKS, 256>>>(
        h, eW1, nW2, nb2, Wih, bih, Whh, bhh);
    edge_gru_kernel<<<NNODE, 256>>>(h, x, rij, dij, mask,
                                    eW1, eb1, eW2, eb2, eW3, eb3,
                                    pW1, pb1, pW2, pb2, nW1, nb1, out);
}

// round 11
// speedup vs baseline: 1.5739x; 1.1629x over previous
#include <cuda_runtime.h>

// EGNN layer, B=4, N=512, D=64, H=1.
// R11: edge kernel de-overheading. R10 profile: issue=43%, DRAM=24%, fma=13%
// -> instruction-overhead bound. Changes: scalar weights packed into 3 float4
// (g_C4), eb1 folded into g_a, 4 edges/thread with pure float4 loads,
// 128-thread blocks.

#define BB 4
#define NN 512
#define DD 64
#define NNODE (BB * NN)

#define GH_BLOCKS    128
#define PQ_BLOCKS    24
#define CONST_BLOCK  (GH_BLOCKS + PQ_BLOCKS)
#define NODES_PER_GH 16

__device__ float  g_a  [NNODE];          // dot(h_i, eW1[0:D]) + eb1
__device__ float  g_bb [NNODE];          // dot(h_j, eW1[D:2D])
__device__ float  g_gh [NNODE * 3 * DD]; // bhh + Whh @ h per node
__device__ float  g_P  [3 * DD];
__device__ float  g_Q  [3 * DD];
__device__ float4 g_C4 [3];              // packed edge-MLP scalars

__device__ __forceinline__ float tanh_ap(float x) {
    float y;
    asm("tanh.approx.f32 %0, %1;" : "=f"(y) : "f"(x));
    return y;
}
__device__ __forceinline__ float sigmoid_f(float x) {
    return fmaf(tanh_ap(0.5f * x), 0.5f, 0.5f);
}
__device__ __forceinline__ float silu_f(float x) {
    return x * sigmoid_f(x);
}

// ---------------------------------------------------------------------------
// Kernel 1: prep (153 blocks).
//   [0,128):  gh GEMM (16 nodes) + node projections a/b
//   [128,152): P/Q
//   152:      pack g_C4
// ---------------------------------------------------------------------------
__global__ __launch_bounds__(256) void prep_kernel(
    const float* __restrict__ h,   const float* __restrict__ eW1,
    const float* __restrict__ eb1,
    const float* __restrict__ nW2, const float* __restrict__ nb2,
    const float* __restrict__ Wih, const float* __restrict__ bih,
    const float* __restrict__ Whh, const float* __restrict__ bhh,
    const float* __restrict__ eW2, const float* __restrict__ eb2,
    const float* __restrict__ eW3, const float* __restrict__ eb3,
    const float* __restrict__ pW1, const float* __restrict__ pb1,
    const float* __restrict__ pW2, const float* __restrict__ pb2,
    const float* __restrict__ nW1, const float* __restrict__ nb1)
{
    const int tid = threadIdx.x;
    const int bid = blockIdx.x;

    if (bid < GH_BLOCKS) {
        __shared__ float wsh[(3 * DD) * 32];    // 24 KB, XOR-swizzled
        __shared__ float hs[NODES_PER_GH * DD]; // 4 KB
        __shared__ float se1[2 * DD];

        const int node0 = bid * NODES_PER_GH;
        {
            const float4* h4 = (const float4*)(h + (size_t)node0 * DD);
            ((float4*)hs)[tid] = h4[tid];
            if (tid < 2 * DD) se1[tid] = eW1[tid];
            #pragma unroll
            for (int i = 0; i < 6; i++) {
                const int e4 = tid + i * 256;
                const int r  = e4 >> 3;
                const int k4 = (e4 & 7) * 4;
                const float4 v = *(const float4*)(Whh + (size_t)r * DD + k4);
                const int rx = r & 31;
                wsh[r * 32 + ((k4 + 0) ^ rx)] = v.x;
                wsh[r * 32 + ((k4 + 1) ^ rx)] = v.y;
                wsh[r * 32 + ((k4 + 2) ^ rx)] = v.z;
                wsh[r * 32 + ((k4 + 3) ^ rx)] = v.w;
            }
        }
        __syncthreads();

        float acc[NODES_PER_GH];
        if (tid < 3 * DD) {
            const int r  = tid;
            const int rx = r & 31;
            const float* wr = wsh + r * 32;
            #pragma unroll
            for (int n = 0; n < NODES_PER_GH; n++) acc[n] = 0.f;
            #pragma unroll 8
            for (int k = 0; k < 32; k++) {
                const float w = wr[k ^ rx];
                #pragma unroll
                for (int n = 0; n < NODES_PER_GH; n++)
                    acc[n] = fmaf(w, hs[n * DD + k], acc[n]);
            }
        } else {
            const int u     = tid - 3 * DD;
            const int dot   = u >> 1;
            const int n     = dot >> 1;
            const int which = dot & 1;
            const int k0    = (u & 1) * 32;
            float p = 0.f;
            const float* hv = hs + n * DD + k0;
            const float* wv = se1 + which * DD + k0;
            #pragma unroll 8
            for (int kk = 0; kk < 32; kk++)
                p = fmaf(hv[kk], wv[kk], p);
            p += __shfl_down_sync(0xffffffffu, p, 1);
            if ((u & 1) == 0) {
                if (which == 0) g_a [node0 + n] = p + eb1[0];
                else            g_bb[node0 + n] = p;
            }
        }
        __syncthreads();

        #pragma unroll
        for (int i = 0; i < 6; i++) {
            const int e4 = tid + i * 256;
            const int r  = e4 >> 3;
            const int k4 = (e4 & 7) * 4;
            const float4 v = *(const float4*)(Whh + (size_t)r * DD + 32 + k4);
            const int rx = r & 31;
            wsh[r * 32 + ((k4 + 0) ^ rx)] = v.x;
            wsh[r * 32 + ((k4 + 1) ^ rx)] = v.y;
            wsh[r * 32 + ((k4 + 2) ^ rx)] = v.z;
            wsh[r * 32 + ((k4 + 3) ^ rx)] = v.w;
        }
        __syncthreads();

        if (tid < 3 * DD) {
            const int r  = tid;
            const int rx = r & 31;
            const float* wr = wsh + r * 32;
            #pragma unroll 8
            for (int k = 0; k < 32; k++) {
                const float w = wr[k ^ rx];
                #pragma unroll
                for (int n = 0; n < NODES_PER_GH; n++)
                    acc[n] = fmaf(w, hs[n * DD + 32 + k], acc[n]);
            }
            const float bh = bhh[r];
            #pragma unroll
            for (int n = 0; n < NODES_PER_GH; n++)
                g_gh[(size_t)(node0 + n) * (3 * DD) + r] = acc[n] + bh;
        }
    } else if (bid < CONST_BLOCK) {
        const int warp = (bid - GH_BLOCKS) * 8 + (tid >> 5);
        const int lane = tid & 31;
        if (warp < 3 * DD) {
            const float* __restrict__ Wr = Wih + (size_t)warp * DD;
            const float w0 = Wr[lane], w1 = Wr[32 + lane];
            float p = fmaf(w1, nW2[32 + lane], w0 * nW2[lane]);
            float q = fmaf(w1, (float)NN * nb2[32 + lane],
                           w0 * ((float)NN * nb2[lane]));
            #pragma unroll
            for (int o = 16; o > 0; o >>= 1) {
                p += __shfl_down_sync(0xffffffffu, p, o);
                q += __shfl_down_sync(0xffffffffu, q, o);
            }
            if (lane == 0) {
                g_P[warp] = p;
                g_Q[warp] = q + bih[warp];
            }
        }
    } else {
        if (tid == 0) {
            g_C4[0] = make_float4(eW1[2 * DD], eW2[0], eb2[0], eW3[0]);
            g_C4[1] = make_float4(eb3[0], pW1[0], pb1[0], pW2[0]);
            g_C4[2] = make_float4(pb2[0], nW1[0], nb1[0], 0.f);
        }
    }
}

// ---------------------------------------------------------------------------
__device__ __forceinline__ void edge_eval(
    float s_pre, float mij,
    float4 c0, float4 c1, float4 c2,
    float& ph, float& v)
{
    const float u  = silu_f(fmaf(silu_f(s_pre), c0.y, c0.z));
    const float mu = fmaf(u, c0.w, c1.x) * mij;
    ph = fmaf(silu_f(fmaf(mu, c1.y, c1.z)), c1.w, c2.x);
    v  = silu_f(fmaf(mu, c2.y, c2.z));
}

// ---------------------------------------------------------------------------
// Kernel 2: edge + x_new + GRU gates.  One node per block, 128 threads,
// 4 edges/thread, float4 loads throughout.
// ---------------------------------------------------------------------------
__global__ __launch_bounds__(128) void edge_gru_kernel(
    const float* __restrict__ h,
    const float* __restrict__ x,
    const float* __restrict__ rij,
    const float* __restrict__ dij,
    const float* __restrict__ mask,
    float* __restrict__ out)
{
    const int node = blockIdx.x;
    const int b    = node / NN;
    const int tid  = threadIdx.x;

    __shared__ float red[4][4];
    __shared__ float hs[DD];
    __shared__ float sS;

    if (tid < DD) hs[tid] = h[node * DD + tid];

    const float4 c0 = g_C4[0];
    const float4 c1 = g_C4[1];
    const float4 c2 = g_C4[2];

    const float mi  = mask[node];
    const float aib = g_a[node];          // includes +eb1

    const float4* __restrict__ d4 = (const float4*)(dij + (size_t)node * NN);
    const float4* __restrict__ r4 = (const float4*)(rij + (size_t)node * NN * 3);
    const float4* __restrict__ b4 = (const float4*)(g_bb + b * NN);
    const float4* __restrict__ k4 = (const float4*)(mask + b * NN);

    const float4 dv = d4[tid];
    const float4 bv = b4[tid];
    const float4 kv = k4[tid];
    const float4 A  = r4[3 * tid + 0];
    const float4 Bv = r4[3 * tid + 1];
    const float4 Cv = r4[3 * tid + 2];

    float ph0, ph1, ph2, ph3, v0, v1, v2, v3;
    edge_eval(fmaf(dv.x, c0.x, aib + bv.x), mi * kv.x, c0, c1, c2, ph0, v0);
    edge_eval(fmaf(dv.y, c0.x, aib + bv.y), mi * kv.y, c0, c1, c2, ph1, v1);
    edge_eval(fmaf(dv.z, c0.x, aib + bv.z), mi * kv.z, c0, c1, c2, ph2, v2);
    edge_eval(fmaf(dv.w, c0.x, aib + bv.w), mi * kv.w, c0, c1, c2, ph3, v3);

    float S  = (v0 + v1) + (v2 + v3);
    float x0 = A.x * ph0;
    float x1 = A.y * ph0;
    float x2 = A.z * ph0;
    x0 = fmaf(A.w,  ph1, x0);
    x1 = fmaf(Bv.x, ph1, x1);
    x2 = fmaf(Bv.y, ph1, x2);
    x0 = fmaf(Bv.z, ph2, x0);
    x1 = fmaf(Bv.w, ph2, x1);
    x2 = fmaf(Cv.x, ph2, x2);
    x0 = fmaf(Cv.y, ph3, x0);
    x1 = fmaf(Cv.z, ph3, x1);
    x2 = fmaf(Cv.w, ph3, x2);

    #pragma unroll
    for (int o = 16; o > 0; o >>= 1) {
        x0 += __shfl_down_sync(0xffffffffu, x0, o);
        x1 += __shfl_down_sync(0xffffffffu, x1, o);
        x2 += __shfl_down_sync(0xffffffffu, x2, o);
        S  += __shfl_down_sync(0xffffffffu, S , o);
    }
    const int wid = tid >> 5;
    if ((tid & 31) == 0) {
        red[wid][0] = x0; red[wid][1] = x1; red[wid][2] = x2; red[wid][3] = S;
    }
    __syncthreads();
    if (tid == 0) {
        float r0 = (red[0][0] + red[1][0]) + (red[2][0] + red[3][0]);
        float r1 = (red[0][1] + red[1][1]) + (red[2][1] + red[3][1]);
        float r2 = (red[0][2] + red[1][2]) + (red[2][2] + red[3][2]);
        float rs = (red[0][3] + red[1][3]) + (red[2][3] + red[3][3]);
        sS = rs;
        float* xo = out + (size_t)NNODE * DD + (size_t)node * 3;
        xo[0] = x[node * 3 + 0] + r0;
        xo[1] = x[node * 3 + 1] + r1;
        xo[2] = x[node * 3 + 2] + r2;
    }
    __syncthreads();

    // GRU gates: gh precomputed, gi rank-1 in S
    if (tid < DD) {
        const int d  = tid;
        const float Sv = sS;
        const float* gh = g_gh + (size_t)node * (3 * DD);
        const float ghr = gh[d];
        const float ghz = gh[DD + d];
        const float ghn = gh[2 * DD + d];
        const float gir = fmaf(Sv, g_P[d],          g_Q[d]);
        const float giz = fmaf(Sv, g_P[DD + d],     g_Q[DD + d]);
        const float gin = fmaf(Sv, g_P[2 * DD + d], g_Q[2 * DD + d]);
        const float r = sigmoid_f(gir + ghr);
        const float z = sigmoid_f(giz + ghz);
        const float n = tanh_ap(fmaf(r, ghn, gin));
        const float hnew = (1.0f - z) * n + z * hs[d];
        out[node * DD + d] = hnew * mi;
    }
}

// ---------------------------------------------------------------------------
extern "C" void kernel_launch(void* const* d_in, const int* in_sizes, int n_in,
                              void* d_out, int out_size) {
    const float* h    = (const float*)d_in[0];
    const float* x    = (const float*)d_in[1];
    const float* rij  = (const float*)d_in[2];
    const float* dij  = (const float*)d_in[3];
    const float* mask = (const float*)d_in[4];
    const float* eW1  = (const float*)d_in[5];
    const float* eb1  = (const float*)d_in[6];
    const float* eW2  = (const float*)d_in[7];
    const float* eb2  = (const float*)d_in[8];
    const float* eW3  = (const float*)d_in[9];
    const float* eb3  = (const float*)d_in[10];
    const float* pW1  = (const float*)d_in[11];
    const float* pb1  = (const float*)d_in[12];
    const float* pW2  = (const float*)d_in[13];
    const float* pb2  = (const float*)d_in[14];
    const float* nW1  = (const float*)d_in[15];
    const float* nb1  = (const float*)d_in[16];
    const float* nW2  = (const float*)d_in[17];
    const float* nb2  = (const float*)d_in[18];
    const float* Wih  = (const float*)d_in[19];
    const float* bih  = (const float*)d_in[20];
    const float* Whh  = (const float*)d_in[21];
    const float* bhh  = (const float*)d_in[22];
    float* out = (float*)d_out;

    prep_kernel<<<CONST_BLOCK + 1, 256>>>(
        h, eW1, eb1, nW2, nb2, Wih, bih, Whh, bhh,
        eW2, eb2, eW3, eb3, pW1, pb1, pW2, pb2, nW1, nb1);
    edge_gru_kernel<<<NNODE, 128>>>(h, x, rij, dij, mask, out);
}